// round 15
// baseline (speedup 1.0000x reference)
#include <cuda_runtime.h>
#include <math.h>

#define DEG   16
#define D     64
#define D2    128
#define BQ    1024
#define NQ    2058
#define XPAD  20           /* slot-dim stride (words): conflict-free quads */
#define GRID  (NQ / 2)     /* 1029 blocks, 2 queries each, exact */

/* dynamic smem layout (float offsets) */
#define OFF_XQ   0                       /* [2][128][20] = 5120  */
#define OFF_PR   5120                    /* [2][4][64][20] = 10240 */
#define OFF_PART 15360                   /* [2][4][64] = 512 */
#define OFF_X2I  15872                   /* 128 float2 = 256 */
#define OFF_YS   16128                   /* [2][128] = 256 */
#define OFF_RED  16384                   /* [2][8] = 16 */
#define OFF_INV  16400                   /* 2 */
#define SMEM_FLOATS 16404
#define SMEM_BYTES  (SMEM_FLOATS * 4)

// ---- packed f32x2 helpers -------------------------------------------------
__device__ __forceinline__ unsigned long long pack2(float a, float b) {
    unsigned long long r;
    asm("mov.b64 %0, {%1, %2};" : "=l"(r) : "f"(a), "f"(b));
    return r;
}
__device__ __forceinline__ void fma2(unsigned long long& acc,
                                     unsigned long long w,
                                     unsigned long long x) {
    asm("fma.rn.f32x2 %0, %1, %2, %0;" : "+l"(acc) : "l"(w), "l"(x));
}
__device__ __forceinline__ float tanha(float x) {
    float y;
    asm("tanh.approx.f32 %0, %1;" : "=f"(y) : "f"(x));
    return y;
}

__device__ __forceinline__ int qnode_of(int q,
                                        const int* __restrict__ in1,
                                        const int* __restrict__ in2,
                                        const int* __restrict__ neg) {
    return (q < BQ) ? in1[q] : (q < 2 * BQ) ? in2[q - BQ] : neg[q - 2 * BQ];
}

// ---------------------------------------------------------------------------
__global__ __launch_bounds__(256, 3)
void k_all(const float* __restrict__ feat,
           const int*   __restrict__ adj,
           const int*   __restrict__ in1,
           const int*   __restrict__ in2,
           const int*   __restrict__ neg,
           const float* __restrict__ W1,
           const float* __restrict__ b1,
           const float* __restrict__ W2,
           const float* __restrict__ b2,
           float*       __restrict__ out) {
    extern __shared__ __align__(16) float smem[];
    float  (*xq)[2 * D][XPAD]   = (float(*)[2 * D][XPAD])(smem + OFF_XQ);
    float  (*pr)[4][D][XPAD]    = (float(*)[4][D][XPAD])(smem + OFF_PR);
    float  (*part)[4][D]        = (float(*)[4][D])(smem + OFF_PART);
    float2 *x2i                 = (float2*)(smem + OFF_X2I);
    float  (*ys)[D2]            = (float(*)[D2])(smem + OFF_YS);
    float  (*red)[8]            = (float(*)[8])(smem + OFF_RED);
    float  *inv2                = smem + OFF_INV;

    int tid  = threadIdx.x;
    int jj   = tid & 63;         // hop-1 output column (gather/reduce mapping)
    int kk   = tid >> 6;         // i-chunk / slot-quad (0..3)
    int lane = tid & 31;
    int wrp  = tid >> 5;         // 0..7
    int qa   = blockIdx.x * 2;
    int na   = qnode_of(qa,     in1, in2, neg);
    int nb   = qnode_of(qa + 1, in1, in2, neg);

    // ---- self features for hop-2 (interleaved qa/qb) ---------------------
    if (tid < D)
        x2i[tid] = make_float2(feat[na * D + tid], feat[nb * D + tid]);

    // ---- gather both queries: group kk fills slots kk*4..kk*4+3 ----------
    #pragma unroll
    for (int sel = 0; sel < 2; ++sel) {
        int qn = sel ? nb : na;
        int4 nn4 = *(const int4*)(adj + qn * DEG + kk * 4);   // broadcast
        float self[4], nsum[4];
        #pragma unroll
        for (int s = 0; s < 4; ++s) {
            int node = (s == 0) ? nn4.x : (s == 1) ? nn4.y
                     : (s == 2) ? nn4.z : nn4.w;
            self[s] = feat[node * D + jj];
            const int4* a4 = (const int4*)(adj + node * DEG);
            int4 a0 = a4[0], a1 = a4[1], a2 = a4[2], a3 = a4[3];
            float t = feat[a0.x * D + jj] + feat[a0.y * D + jj]
                    + feat[a0.z * D + jj] + feat[a0.w * D + jj];
            t += feat[a1.x * D + jj] + feat[a1.y * D + jj]
               + feat[a1.z * D + jj] + feat[a1.w * D + jj];
            t += feat[a2.x * D + jj] + feat[a2.y * D + jj]
               + feat[a2.z * D + jj] + feat[a2.w * D + jj];
            t += feat[a3.x * D + jj] + feat[a3.y * D + jj]
               + feat[a3.z * D + jj] + feat[a3.w * D + jj];
            nsum[s] = t;
        }
        *(float4*)&xq[sel][jj][kk * 4]     = make_float4(self[0], self[1], self[2], self[3]);
        *(float4*)&xq[sel][D + jj][kk * 4] = make_float4(nsum[0], nsum[1], nsum[2], nsum[3]);
    }
    __syncthreads();                                    // A: xq ready

    // ---- hop-1 GEMV, warp-specialized: warp = (sel, chunk-group) ---------
    // sel = wrp&1, cgrp = wrp>>1; i ranges [16*cgrp,+16) and [64+16*cgrp,+16)
    // thread covers j = lane and lane+32 for ALL 16 slots.
    {
        int gsel = wrp & 1;
        int cgrp = wrp >> 1;
        unsigned long long accA[8], accB[8];
        #pragma unroll
        for (int s = 0; s < 8; ++s) { accA[s] = 0ull; accB[s] = 0ull; }

        #pragma unroll
        for (int half = 0; half < 2; ++half) {
            int ibase = cgrp * 16 + half * 64;
            #pragma unroll
            for (int sub = 0; sub < 2; ++sub) {
                int i0 = ibase + sub * 8;
                const float4* pA = (const float4*)(W1 + lane * (2 * D) + i0);
                const float4* pB = (const float4*)(W1 + (lane + 32) * (2 * D) + i0);
                float4 wa0 = __ldg(pA), wa1 = __ldg(pA + 1);
                float4 wb0 = __ldg(pB), wb1 = __ldg(pB + 1);
                float wA[8] = {wa0.x, wa0.y, wa0.z, wa0.w,
                               wa1.x, wa1.y, wa1.z, wa1.w};
                float wB[8] = {wb0.x, wb0.y, wb0.z, wb0.w,
                               wb1.x, wb1.y, wb1.z, wb1.w};
                #pragma unroll
                for (int m = 0; m < 8; ++m) {
                    int i = i0 + m;
                    ulonglong2 x01 = *(const ulonglong2*)&xq[gsel][i][0];
                    ulonglong2 x23 = *(const ulonglong2*)&xq[gsel][i][4];
                    ulonglong2 x45 = *(const ulonglong2*)&xq[gsel][i][8];
                    ulonglong2 x67 = *(const ulonglong2*)&xq[gsel][i][12];
                    unsigned long long wdA = pack2(wA[m], wA[m]);
                    unsigned long long wdB = pack2(wB[m], wB[m]);
                    fma2(accA[0], wdA, x01.x); fma2(accA[1], wdA, x01.y);
                    fma2(accA[2], wdA, x23.x); fma2(accA[3], wdA, x23.y);
                    fma2(accA[4], wdA, x45.x); fma2(accA[5], wdA, x45.y);
                    fma2(accA[6], wdA, x67.x); fma2(accA[7], wdA, x67.y);
                    fma2(accB[0], wdB, x01.x); fma2(accB[1], wdB, x01.y);
                    fma2(accB[2], wdB, x23.x); fma2(accB[3], wdB, x23.y);
                    fma2(accB[4], wdB, x45.x); fma2(accB[5], wdB, x45.y);
                    fma2(accB[6], wdB, x67.x); fma2(accB[7], wdB, x67.y);
                }
            }
        }
        #pragma unroll
        for (int q4 = 0; q4 < 4; ++q4) {
            *(ulonglong2*)&pr[gsel][cgrp][lane][q4 * 4] =
                make_ulonglong2(accA[2 * q4], accA[2 * q4 + 1]);
            *(ulonglong2*)&pr[gsel][cgrp][lane + 32][q4 * 4] =
                make_ulonglong2(accB[2 * q4], accB[2 * q4 + 1]);
        }
    }
    __syncthreads();                                    // B: pr ready (both)

    // ---- reduce chunks, +bias, tanh, sum slot-quad (both sels) -----------
    {
        float bb1 = __ldg(&b1[jj]);
        #pragma unroll
        for (int sel = 0; sel < 2; ++sel) {
            float4 v0 = *(const float4*)&pr[sel][0][jj][kk * 4];
            float4 v1 = *(const float4*)&pr[sel][1][jj][kk * 4];
            float4 v2 = *(const float4*)&pr[sel][2][jj][kk * 4];
            float4 v3 = *(const float4*)&pr[sel][3][jj][kk * 4];
            part[sel][kk][jj] = tanha((v0.x + v1.x) + (v2.x + v3.x) + bb1)
                              + tanha((v0.y + v1.y) + (v2.y + v3.y) + bb1)
                              + tanha((v0.z + v1.z) + (v2.z + v3.z) + bb1)
                              + tanha((v0.w + v1.w) + (v2.w + v3.w) + bb1);
        }
    }
    __syncthreads();                                    // C: part ready

    // ---- build hop-2 sum2 (interleaved) ----------------------------------
    if (tid < D) {
        float sa = (part[0][0][tid] + part[0][1][tid])
                 + (part[0][2][tid] + part[0][3][tid]);
        float sb = (part[1][0][tid] + part[1][1][tid])
                 + (part[1][2][tid] + part[1][3][tid]);
        x2i[D + tid] = make_float2(sa, sb);
    }
    __syncthreads();                                    // F: x2i ready

    // ---- hop-2: warp covers 16 cols, 4 cols/pass, 8 lanes/column ---------
    {
        int oct = lane & 7;
        int sub = lane >> 3;

        float4 xv[8];
        #pragma unroll
        for (int k = 0; k < 4; ++k) {
            xv[2 * k]     = *(const float4*)&x2i[oct * 4 + k * 32];
            xv[2 * k + 1] = *(const float4*)&x2i[oct * 4 + k * 32 + 2];
        }

        float sqa = 0.f, sqb = 0.f;
        #pragma unroll
        for (int p = 0; p < 4; ++p) {
            int c = wrp * 16 + p * 4 + sub;
            float pa = 0.f, pb = 0.f;
            #pragma unroll
            for (int k = 0; k < 4; ++k) {
                float4 wv = __ldg((const float4*)(W2 + c * (2 * D) + k * 32) + oct);
                float4 v0 = xv[2 * k], v1 = xv[2 * k + 1];
                pa += wv.x * v0.x + wv.y * v0.z + wv.z * v1.x + wv.w * v1.z;
                pb += wv.x * v0.y + wv.y * v0.w + wv.z * v1.y + wv.w * v1.w;
            }
            #pragma unroll
            for (int off = 1; off <= 4; off <<= 1) {
                pa += __shfl_xor_sync(0xffffffffu, pa, off);
                pb += __shfl_xor_sync(0xffffffffu, pb, off);
            }
            float bbc = __ldg(&b2[c]);
            pa += bbc; pb += bbc;
            if (oct == 0) {
                ys[0][c] = pa; ys[1][c] = pb;
                sqa += pa * pa; sqb += pb * pb;
            }
        }
        sqa += __shfl_xor_sync(0xffffffffu, sqa, 8);
        sqb += __shfl_xor_sync(0xffffffffu, sqb, 8);
        sqa += __shfl_xor_sync(0xffffffffu, sqa, 16);
        sqb += __shfl_xor_sync(0xffffffffu, sqb, 16);
        if (lane == 0) { red[0][wrp] = sqa; red[1][wrp] = sqb; }
    }
    __syncthreads();                                    // G: ys/red ready

    if (tid < 2) {
        float t = ((red[tid][0] + red[tid][1]) + (red[tid][2] + red[tid][3]))
                + ((red[tid][4] + red[tid][5]) + (red[tid][6] + red[tid][7]));
        inv2[tid] = 1.0f / fmaxf(sqrtf(t), 1e-12f);
    }
    __syncthreads();                                    // H: inv ready

    {
        int qsel = tid >> 7;
        int col  = tid & 127;
        out[(qa + qsel) * D2 + col] = ys[qsel][col] * inv2[qsel];
    }
}

// ---------------------------------------------------------------------------
extern "C" void kernel_launch(void* const* d_in, const int* in_sizes, int n_in,
                              void* d_out, int out_size) {
    const float* feat = (const float*)d_in[0];   // [65536, 64]
    const int*   adj  = (const int*)  d_in[1];   // [65536, 16]
    const int*   in1  = (const int*)  d_in[2];   // [1024]
    const int*   in2  = (const int*)  d_in[3];   // [1024]
    const int*   neg  = (const int*)  d_in[4];   // [10]
    const float* W1   = (const float*)d_in[5];   // [64, 128]
    const float* b1   = (const float*)d_in[6];   // [64]
    const float* W2   = (const float*)d_in[7];   // [128, 128]
    const float* b2   = (const float*)d_in[8];   // [128]
    float*       out  = (float*)d_out;           // [2058, 128]

    cudaFuncSetAttribute(k_all, cudaFuncAttributeMaxDynamicSharedMemorySize,
                         SMEM_BYTES);
    k_all<<<GRID, 256, SMEM_BYTES>>>(feat, adj, in1, in2, neg,
                                     W1, b1, W2, b2, out);
}

// round 16
// speedup vs baseline: 1.0484x; 1.0484x over previous
#include <cuda_runtime.h>
#include <math.h>

#define DEG   16
#define D     64
#define D2    128
#define BQ    1024
#define NQ    2058
#define XPAD  20           /* xq/pr slot-dim stride (words) */
#define GRID  (NQ / 2)     /* 1029 blocks, 2 queries each */

/* dynamic smem layout (float offsets) */
#define OFF_XQ   0                       /* [2][128][20] = 5120  */
#define OFF_PR   5120                    /* [2][4][64][20] = 10240 ; gather scratch reuses */
#define OFF_PART 15360                   /* [2][4][64] = 512 */
#define OFF_X2I  15872                   /* 128 float2 = 256 */
#define OFF_YS   16128                   /* [2][128] = 256 */
#define OFF_RED  16384                   /* [2][8] = 16 */
#define OFF_INV  16400                   /* 2 */
#define SMEM_FLOATS 16404
#define SMEM_BYTES  (SMEM_FLOATS * 4)

// ---- packed f32x2 helpers -------------------------------------------------
__device__ __forceinline__ unsigned long long pack2(float a, float b) {
    unsigned long long r;
    asm("mov.b64 %0, {%1, %2};" : "=l"(r) : "f"(a), "f"(b));
    return r;
}
__device__ __forceinline__ void fma2(unsigned long long& acc,
                                     unsigned long long w,
                                     unsigned long long x) {
    asm("fma.rn.f32x2 %0, %1, %2, %0;" : "+l"(acc) : "l"(w), "l"(x));
}
__device__ __forceinline__ float tanha(float x) {
    float y;
    asm("tanh.approx.f32 %0, %1;" : "=f"(y) : "f"(x));
    return y;
}

__device__ __forceinline__ int qnode_of(int q,
                                        const int* __restrict__ in1,
                                        const int* __restrict__ in2,
                                        const int* __restrict__ neg) {
    return (q < BQ) ? in1[q] : (q < 2 * BQ) ? in2[q - BQ] : neg[q - 2 * BQ];
}

// ---------------------------------------------------------------------------
__global__ __launch_bounds__(256, 3)
void k_all(const float* __restrict__ feat,
           const int*   __restrict__ adj,
           const int*   __restrict__ in1,
           const int*   __restrict__ in2,
           const int*   __restrict__ neg,
           const float* __restrict__ W1,
           const float* __restrict__ b1,
           const float* __restrict__ W2,
           const float* __restrict__ b2,
           float*       __restrict__ out) {
    extern __shared__ __align__(16) float smem[];
    float  (*xq)[2 * D][XPAD]   = (float(*)[2 * D][XPAD])(smem + OFF_XQ);
    float  (*pr)[4][D][XPAD]    = (float(*)[4][D][XPAD])(smem + OFF_PR);
    float  (*part)[4][D]        = (float(*)[4][D])(smem + OFF_PART);
    float2 *x2i                 = (float2*)(smem + OFF_X2I);
    float  (*ys)[D2]            = (float(*)[D2])(smem + OFF_YS);
    float  (*red)[8]            = (float(*)[8])(smem + OFF_RED);
    float  *inv2                = smem + OFF_INV;

    int tid  = threadIdx.x;
    int jj   = tid & 63;         // hop-1 output column (GEMV/reduce mapping)
    int kk   = tid >> 6;         // i-chunk / slot-quad (0..3)
    int lane = tid & 31;
    int wrp  = tid >> 5;         // 0..7
    int qa   = blockIdx.x * 2;
    int na   = qnode_of(qa,     in1, in2, neg);
    int nb   = qnode_of(qa + 1, in1, in2, neg);

    // ---- self features for hop-2 (interleaved qa/qb), wide loads ---------
    if (tid < 32) {
        int f2 = tid & 15, h2 = tid >> 4;
        float4 v = __ldg((const float4*)(feat + (h2 ? nb : na) * D) + f2);
        float* dst = (float*)&x2i[4 * f2] + h2;   // .x (qa) or .y (qb)
        dst[0] = v.x; dst[2] = v.y; dst[4] = v.z; dst[6] = v.w;
    }

    // ---- WIDE gather: warp = (sel, slot-quad); float4 rows ---------------
    // 16-lane half loads one slot's full rows; smem transpose into xq.
    {
        int gsel = wrp >> 2;     // 0..1 : which query
        int quad = wrp & 3;      // 0..3 : slot quad
        int half = lane >> 4;    // slot within pass
        int f    = lane & 15;    // float4 position in 64-float row
        int qn   = gsel ? nb : na;
        int4 nn4 = __ldg((const int4*)(adj + qn * DEG) + quad);
        float* scr = smem + OFF_PR;   // scratch [32 cols][2 sets][68], < pr size

        #pragma unroll
        for (int p = 0; p < 2; ++p) {
            int node = p ? (half ? nn4.w : nn4.z) : (half ? nn4.y : nn4.x);
            int col  = quad * 4 + 2 * p + half;
            const int4* arow = (const int4*)(adj + node * DEG);
            int4 a0 = __ldg(arow),     a1 = __ldg(arow + 1);
            int4 a2 = __ldg(arow + 2), a3 = __ldg(arow + 3);
            float4 self4 = __ldg((const float4*)(feat + node * D) + f);
            int ids[16] = {a0.x, a0.y, a0.z, a0.w,  a1.x, a1.y, a1.z, a1.w,
                           a2.x, a2.y, a2.z, a2.w,  a3.x, a3.y, a3.z, a3.w};
            float4 acc = make_float4(0.f, 0.f, 0.f, 0.f);
            #pragma unroll
            for (int k = 0; k < 16; ++k) {
                float4 v = __ldg((const float4*)(feat + ids[k] * D) + f);
                acc.x += v.x; acc.y += v.y; acc.z += v.z; acc.w += v.w;
            }
            float* bse = scr + ((gsel * 16 + col) * 2) * 68 + 4 * f;
            *(float4*)bse        = self4;   // set 0
            *(float4*)(bse + 68) = acc;     // set 1
        }
        __syncwarp();

        // transpose: lane j collects 4-slot vector per row, STS.128 into xq
        int cb = (gsel * 16 + quad * 4) * 2;
        #pragma unroll
        for (int jh = 0; jh < 2; ++jh) {
            int j = lane + 32 * jh;
            #pragma unroll
            for (int set = 0; set < 2; ++set) {
                int b0 = (cb + set) * 68 + j;
                float v0 = scr[b0];
                float v1 = scr[b0 + 136];
                float v2 = scr[b0 + 272];
                float v3 = scr[b0 + 408];
                int row = set ? (D + j) : j;
                *(float4*)&xq[gsel][row][quad * 4] = make_float4(v0, v1, v2, v3);
            }
        }
    }

    // ---- W1 chunk into registers -----------------------------------------
    float Wreg[32];
    {
        const float4* ws = (const float4*)(W1 + jj * (2 * D) + kk * 32);
        #pragma unroll
        for (int r = 0; r < 8; ++r) {
            float4 v = __ldg(&ws[r]);
            Wreg[r * 4 + 0] = v.x; Wreg[r * 4 + 1] = v.y;
            Wreg[r * 4 + 2] = v.z; Wreg[r * 4 + 3] = v.w;
        }
    }
    float bb1 = __ldg(&b1[jj]);
    __syncthreads();                                    // A: xq ready

    // ---- GEMV both sels back-to-back (pr double-buffered) ----------------
    #pragma unroll
    for (int sel = 0; sel < 2; ++sel) {
        unsigned long long acc[8];
        #pragma unroll
        for (int s = 0; s < 8; ++s) acc[s] = 0ull;
        #pragma unroll
        for (int m = 0; m < 32; ++m) {
            int i = kk * 32 + m;
            unsigned long long wd = pack2(Wreg[m], Wreg[m]);
            ulonglong2 x01 = *(const ulonglong2*)&xq[sel][i][0];
            ulonglong2 x23 = *(const ulonglong2*)&xq[sel][i][4];
            ulonglong2 x45 = *(const ulonglong2*)&xq[sel][i][8];
            ulonglong2 x67 = *(const ulonglong2*)&xq[sel][i][12];
            fma2(acc[0], wd, x01.x); fma2(acc[1], wd, x01.y);
            fma2(acc[2], wd, x23.x); fma2(acc[3], wd, x23.y);
            fma2(acc[4], wd, x45.x); fma2(acc[5], wd, x45.y);
            fma2(acc[6], wd, x67.x); fma2(acc[7], wd, x67.y);
        }
        *(ulonglong2*)&pr[sel][kk][jj][0]  = make_ulonglong2(acc[0], acc[1]);
        *(ulonglong2*)&pr[sel][kk][jj][4]  = make_ulonglong2(acc[2], acc[3]);
        *(ulonglong2*)&pr[sel][kk][jj][8]  = make_ulonglong2(acc[4], acc[5]);
        *(ulonglong2*)&pr[sel][kk][jj][12] = make_ulonglong2(acc[6], acc[7]);
    }
    __syncthreads();                                    // B: pr ready (both)

    // ---- reduce chunks, +bias, tanh, sum slot-quad (both sels) -----------
    #pragma unroll
    for (int sel = 0; sel < 2; ++sel) {
        float4 v0 = *(const float4*)&pr[sel][0][jj][kk * 4];
        float4 v1 = *(const float4*)&pr[sel][1][jj][kk * 4];
        float4 v2 = *(const float4*)&pr[sel][2][jj][kk * 4];
        float4 v3 = *(const float4*)&pr[sel][3][jj][kk * 4];
        part[sel][kk][jj] = tanha((v0.x + v1.x) + (v2.x + v3.x) + bb1)
                          + tanha((v0.y + v1.y) + (v2.y + v3.y) + bb1)
                          + tanha((v0.z + v1.z) + (v2.z + v3.z) + bb1)
                          + tanha((v0.w + v1.w) + (v2.w + v3.w) + bb1);
    }
    __syncthreads();                                    // C: part ready

    // ---- build hop-2 sum2 (interleaved) ----------------------------------
    if (tid < D) {
        float sa = (part[0][0][tid] + part[0][1][tid])
                 + (part[0][2][tid] + part[0][3][tid]);
        float sb = (part[1][0][tid] + part[1][1][tid])
                 + (part[1][2][tid] + part[1][3][tid]);
        x2i[D + tid] = make_float2(sa, sb);
    }
    __syncthreads();                                    // F: x2i ready

    // ---- hop-2: warp covers 16 cols, 4 cols/pass, 8 lanes/column ---------
    {
        int oct = lane & 7;
        int sub = lane >> 3;

        float4 xv[8];
        #pragma unroll
        for (int k = 0; k < 4; ++k) {
            xv[2 * k]     = *(const float4*)&x2i[oct * 4 + k * 32];
            xv[2 * k + 1] = *(const float4*)&x2i[oct * 4 + k * 32 + 2];
        }

        float sqa = 0.f, sqb = 0.f;
        #pragma unroll
        for (int p = 0; p < 4; ++p) {
            int c = wrp * 16 + p * 4 + sub;
            float pa = 0.f, pb = 0.f;
            #pragma unroll
            for (int k = 0; k < 4; ++k) {
                float4 wv = __ldg((const float4*)(W2 + c * (2 * D) + k * 32) + oct);
                float4 v0 = xv[2 * k], v1 = xv[2 * k + 1];
                pa += wv.x * v0.x + wv.y * v0.z + wv.z * v1.x + wv.w * v1.z;
                pb += wv.x * v0.y + wv.y * v0.w + wv.z * v1.y + wv.w * v1.w;
            }
            #pragma unroll
            for (int off = 1; off <= 4; off <<= 1) {
                pa += __shfl_xor_sync(0xffffffffu, pa, off);
                pb += __shfl_xor_sync(0xffffffffu, pb, off);
            }
            float bbc = __ldg(&b2[c]);
            pa += bbc; pb += bbc;
            if (oct == 0) {
                ys[0][c] = pa; ys[1][c] = pb;
                sqa += pa * pa; sqb += pb * pb;
            }
        }
        sqa += __shfl_xor_sync(0xffffffffu, sqa, 8);
        sqb += __shfl_xor_sync(0xffffffffu, sqb, 8);
        sqa += __shfl_xor_sync(0xffffffffu, sqa, 16);
        sqb += __shfl_xor_sync(0xffffffffu, sqb, 16);
        if (lane == 0) { red[0][wrp] = sqa; red[1][wrp] = sqb; }
    }
    __syncthreads();                                    // G: ys/red ready

    if (tid < 2) {
        float t = ((red[tid][0] + red[tid][1]) + (red[tid][2] + red[tid][3]))
                + ((red[tid][4] + red[tid][5]) + (red[tid][6] + red[tid][7]));
        inv2[tid] = 1.0f / fmaxf(sqrtf(t), 1e-12f);
    }
    __syncthreads();                                    // H: inv ready

    {
        int qsel = tid >> 7;
        int col  = tid & 127;
        out[(qa + qsel) * D2 + col] = ys[qsel][col] * inv2[qsel];
    }
}

// ---------------------------------------------------------------------------
extern "C" void kernel_launch(void* const* d_in, const int* in_sizes, int n_in,
                              void* d_out, int out_size) {
    const float* feat = (const float*)d_in[0];   // [65536, 64]
    const int*   adj  = (const int*)  d_in[1];   // [65536, 16]
    const int*   in1  = (const int*)  d_in[2];   // [1024]
    const int*   in2  = (const int*)  d_in[3];   // [1024]
    const int*   neg  = (const int*)  d_in[4];   // [10]
    const float* W1   = (const float*)d_in[5];   // [64, 128]
    const float* b1   = (const float*)d_in[6];   // [64]
    const float* W2   = (const float*)d_in[7];   // [128, 128]
    const float* b2   = (const float*)d_in[8];   // [128]
    float*       out  = (float*)d_out;           // [2058, 128]

    cudaFuncSetAttribute(k_all, cudaFuncAttributeMaxDynamicSharedMemorySize,
                         SMEM_BYTES);
    k_all<<<GRID, 256, SMEM_BYTES>>>(feat, adj, in1, in2, neg,
                                     W1, b1, W2, b2, out);
}